// round 6
// baseline (speedup 1.0000x reference)
#include <cuda_runtime.h>
#include <stdint.h>
#include <math.h>

// ---------------------------------------------------------------------------
// RandomPhongShader: N=8, H=256, W=256, K=8, NB_SAMPLES=4
// SIGMA=0.1, GAMMA=0.1, ZNEAR=1, ZFAR=100, EPS=1e-10
//
// JAX threefry PRNG, partitionable mode:
//   random_bits(32)[i] = out0 ^ out1 of threefry(key, hi=0, lo=i)
//
// Pipe balancing: threefry's SHF/LOP3 are ALU-pipe-locked (~3.2k ops/pixel);
// ALL of its integer adds are written as a*one+b with `one` a runtime kernel
// param (=1) so ptxas MUST emit IMAD (FMA pipe) and cannot rebalance back to
// IADD3. This equalizes the two pipes (~3.1k ops each). Bit-identical.
//
// Background-prune: zm[8] = (EPS - zmax)/GAMMA <= -10 while max face score
// >= -1.5 whenever any face survives a heaviside sample; |0.1*noise| <= 0.543,
// so if zm[8] < maxzm - 1.25 the background can never win -> skip its 4
// threefry evals (guard is provably decision-preserving, taken w.p. ~2e-10).
// ---------------------------------------------------------------------------

#define NPIX (8 * 256 * 256)          // 524288 pixels
#define STRIDE_H 4194304u             // N*H*W*K     (per-sample stride, noise_h)
#define STRIDE_A 4718592u             // N*H*W*(K+1) (per-sample stride, noise_a)

// add forced onto the FMA pipe (IMAD): one == 1 at runtime, opaque to ptxas
#define IADD(a, b) ((a) * one + (b))

// Full Threefry-2x32 with x0 = 0 (hi), x1 = ctr (lo); returns out0 ^ out1.
__device__ __forceinline__ uint32_t tf_xor(uint32_t k0, uint32_t k1, uint32_t ctr,
                                           uint32_t one)
{
    uint32_t k2 = k0 ^ k1 ^ 0x1BD11BDAu;
    uint32_t x0 = k0;                 // 0 + k0
    uint32_t x1 = IADD(ctr, k1);
#define TFR(r) { x0 = IADD(x0, x1); x1 = __funnelshift_l(x1, x1, (r)); x1 ^= x0; }
    TFR(13) TFR(15) TFR(26) TFR(6)
    x0 = IADD(x0, k1); x1 = IADD(x1, k2 + 1u);
    TFR(17) TFR(29) TFR(16) TFR(24)
    x0 = IADD(x0, k2); x1 = IADD(x1, k0 + 2u);
    TFR(13) TFR(15) TFR(26) TFR(6)
    x0 = IADD(x0, k0); x1 = IADD(x1, k1 + 3u);
    TFR(17) TFR(29) TFR(16) TFR(24)
    x0 = IADD(x0, k1); x1 = IADD(x1, k2 + 4u);
    TFR(13) TFR(15) TFR(26) TFR(6)
    x0 = IADD(x0, k2); x1 = IADD(x1, k0 + 5u);
#undef TFR
    return x0 ^ x1;
}

// Giles erf_inv (same coefficients as XLA), FMA form + MUFU log.
__device__ __forceinline__ float erfinv_fast(float x)
{
    float t = __fmaf_rn(-x, x, 1.0f);          // 1 - x*x
    float w = -__logf(t);                      // MUFU LG2 * ln2
    float p;
    if (w < 5.0f) {
        w = w - 2.5f;
        p = 2.81022636e-08f;
        p = __fmaf_rn(p, w, 3.43273939e-07f);
        p = __fmaf_rn(p, w, -3.5233877e-06f);
        p = __fmaf_rn(p, w, -4.39150654e-06f);
        p = __fmaf_rn(p, w, 0.00021858087f);
        p = __fmaf_rn(p, w, -0.00125372503f);
        p = __fmaf_rn(p, w, -0.00417768164f);
        p = __fmaf_rn(p, w, 0.246640727f);
        p = __fmaf_rn(p, w, 1.50140941f);
    } else {
        w = sqrtf(w) - 3.0f;
        p = -0.000200214257f;
        p = __fmaf_rn(p, w, 0.000100950558f);
        p = __fmaf_rn(p, w, 0.00134934322f);
        p = __fmaf_rn(p, w, -0.00367342844f);
        p = __fmaf_rn(p, w, 0.00573950773f);
        p = __fmaf_rn(p, w, -0.0076224613f);
        p = __fmaf_rn(p, w, 0.00943887047f);
        p = __fmaf_rn(p, w, 1.00167406f);
        p = __fmaf_rn(p, w, 2.83297682f);
    }
    return p * x;
}

// m = bits>>9 -> N(0,1); exact same fp sequence as the reference mapping.
__device__ __forceinline__ float m_to_normal(uint32_t m)
{
    const float LO    = __uint_as_float(0xBF7FFFFFu);  // nextafter(-1, 0)
    const float SQRT2 = __uint_as_float(0x3FB504F3u);  // float32(sqrt(2))
    float u = __fmaf_rn((float)m, 0x1.0p-22f, LO);     // exact prod, 1 rounding
    return SQRT2 * erfinv_fast(u);
}

// Abramowitz-Stegun 7.1.26 erf, |abs err| <= ~1.5e-7 (plus expf/div ~1e-7).
__device__ __forceinline__ float erf_approx(float z)
{
    float az = fminf(fabsf(z), 4.0f);      // erf(4) = 1 - 1.5e-8, saturate
    float t  = __fdividef(1.0f, __fmaf_rn(0.3275911f, az, 1.0f));
    float y  = 1.061405429f;
    y = __fmaf_rn(y, t, -1.453152027f);
    y = __fmaf_rn(y, t,  1.421413741f);
    y = __fmaf_rn(y, t, -0.284496736f);
    y = __fmaf_rn(y, t,  0.254829592f);
    y = y * t;
    float e = __expf(-az * az);
    float r = __fmaf_rn(-y, e, 1.0f);
    return (z < 0.0f) ? -r : r;
}

__global__ void __launch_bounds__(256, 6)
rps_kernel(const float* __restrict__ colors,   // (N,H,W,K,3)
           const float* __restrict__ dists,    // (N,H,W,K)
           const float* __restrict__ zbuf,     // (N,H,W,K)
           const int*   __restrict__ p2f,      // (N,H,W,K)
           const float* __restrict__ bg,       // (3,)
           float*       __restrict__ out,      // (N,H,W,4)
           uint32_t kh0, uint32_t kh1, uint32_t ka0, uint32_t ka1,
           float l0, float l1, float l2, float l3, float l4,
           uint32_t one)
{
    unsigned pix = blockIdx.x * 256u + threadIdx.x;
    if (pix >= NPIX) return;

    // ---- loads (vectorized) ----
    const float4* dv = (const float4*)(dists + (size_t)pix * 8);
    const float4* zv = (const float4*)(zbuf  + (size_t)pix * 8);
    const int4*   fv = (const int4*)  (p2f   + (size_t)pix * 8);
    float4 d0 = dv[0], d1 = dv[1];
    float4 z0 = zv[0], z1 = zv[1];
    int4   f0 = fv[0], f1 = fv[1];

    float dd[8] = {d0.x, d0.y, d0.z, d0.w, d1.x, d1.y, d1.z, d1.w};
    float zz[8] = {z0.x, z0.y, z0.z, z0.w, z1.x, z1.y, z1.z, z1.w};
    int   ff[8] = {f0.x, f0.y, f0.z, f0.w, f1.x, f1.y, f1.z, f1.w};

    // ---- heaviside via integer threshold / prob / alpha / z_inv / log-LUT --
    float logp[8], zinv[8];
    float alpha = 1.0f;
    uint32_t bh = pix * 8u;
#pragma unroll
    for (int k = 0; k < 8; ++k) {
        bool msk = (ff[k] >= 0);
        float mask = msk ? 1.0f : 0.0f;
        uint32_t b = IADD(bh, (uint32_t)k);
        float d = dd[k];
        float x = -d;

        // threshold on m = bits>>9: decision is (m >= m*), |m* - mth| << 64
        float uth = erf_approx(d * 7.0710678f);                 // erf(10d/sqrt2)
        // (uth - LO)*2^22 ; -LO*2^22 = (1-2^-24)*2^22 = 4194303.75 exactly
        int mth = __float2int_rn(__fmaf_rn(uth, 4194304.0f, 4194303.75f));
        int mhi = mth + 64;
        int mlo = mth - 64;

        int cnt = 0;
#pragma unroll
        for (int s = 0; s < 4; ++s) {
            uint32_t bits = tf_xor(kh0, kh1, IADD(b, (uint32_t)s * STRIDE_H), one);
            int m = (int)(bits >> 9);
            if (m >= mhi) {
                cnt++;
            } else if (m > mlo) {   // rare exact fallback (~3e-5 per sample)
                cnt += (__fadd_rn(x, __fmul_rn(0.1f, m_to_normal((uint32_t)m))) >= 0.0f);
            }
        }

        int idx = msk ? cnt : 0;
        float prob = __fmul_rn((float)cnt * 0.25f, mask);   // exact
        alpha = __fmul_rn(alpha, 1.0f - prob);              // exact product
        // log(EPS + prob): prob in {0,.25,.5,.75,1} -> 5-entry select
        float lv = l0;
        lv = (idx == 1) ? l1 : lv;
        lv = (idx == 2) ? l2 : lv;
        lv = (idx == 3) ? l3 : lv;
        lv = (idx == 4) ? l4 : lv;
        logp[k] = lv;
        zinv[k] = __fmul_rn(__fdiv_rn(__fsub_rn(100.0f, zz[k]), 99.0f), mask);
    }

    // ---- z_inv_max (clipped at EPS) ----
    float m = zinv[0];
#pragma unroll
    for (int k = 1; k < 8; ++k) m = fmaxf(m, zinv[k]);
    m = fmaxf(m, 1e-10f);

    // ---- z_map (9 entries incl. background score) ----
    float zm[9];
    float maxzm = -1e30f;
#pragma unroll
    for (int k = 0; k < 8; ++k) {
        zm[k] = __fadd_rn(logp[k], __fdiv_rn(__fsub_rn(zinv[k], m), 0.1f));
        maxzm = fmaxf(maxzm, zm[k]);
    }
    zm[8] = __fdiv_rn(__fsub_rn(1e-10f, m), 0.1f);

    // ---- random argmax: faces j=0..7 (4 samples each, first-max-wins) ----
    float b0 = 0.f, b1 = 0.f, b2 = 0.f, b3 = 0.f;
    int   i0 = 0, i1 = 0, i2 = 0, i3 = 0;
    uint32_t ba = pix * 9u;
#pragma unroll
    for (int j = 0; j < 8; ++j) {
        uint32_t c = IADD(ba, (uint32_t)j);
        float s0 = __fadd_rn(zm[j], __fmul_rn(0.1f, m_to_normal(tf_xor(ka0, ka1, c, one) >> 9)));
        float s1 = __fadd_rn(zm[j], __fmul_rn(0.1f, m_to_normal(tf_xor(ka0, ka1, IADD(c, STRIDE_A), one) >> 9)));
        float s2 = __fadd_rn(zm[j], __fmul_rn(0.1f, m_to_normal(tf_xor(ka0, ka1, IADD(c, 2u * STRIDE_A), one) >> 9)));
        float s3 = __fadd_rn(zm[j], __fmul_rn(0.1f, m_to_normal(tf_xor(ka0, ka1, IADD(c, 3u * STRIDE_A), one) >> 9)));
        if (j == 0) {
            b0 = s0; b1 = s1; b2 = s2; b3 = s3;
        } else {
            if (s0 > b0) { b0 = s0; i0 = j; }
            if (s1 > b1) { b1 = s1; i1 = j; }
            if (s2 > b2) { b2 = s2; i2 = j; }
            if (s3 > b3) { b3 = s3; i3 = j; }
        }
    }
    // Background (j=8): |0.1*noise| <= 0.543; if zm[8] is out of reach of the
    // best face score it can never win -> skip (taken w.p. ~2e-10).
    if (zm[8] > maxzm - 1.25f) {
        uint32_t c = IADD(ba, 8u);
        float s0 = __fadd_rn(zm[8], __fmul_rn(0.1f, m_to_normal(tf_xor(ka0, ka1, c, one) >> 9)));
        float s1 = __fadd_rn(zm[8], __fmul_rn(0.1f, m_to_normal(tf_xor(ka0, ka1, IADD(c, STRIDE_A), one) >> 9)));
        float s2 = __fadd_rn(zm[8], __fmul_rn(0.1f, m_to_normal(tf_xor(ka0, ka1, IADD(c, 2u * STRIDE_A), one) >> 9)));
        float s3 = __fadd_rn(zm[8], __fmul_rn(0.1f, m_to_normal(tf_xor(ka0, ka1, IADD(c, 3u * STRIDE_A), one) >> 9)));
        if (s0 > b0) { i0 = 8; }
        if (s1 > b1) { i1 = 8; }
        if (s2 > b2) { i2 = 8; }
        if (s3 > b3) { i3 = 8; }
    }

    // ---- weighted colors ----
    const float4* cv = (const float4*)(colors + (size_t)pix * 24);
    float4 ca = cv[0], cb = cv[1], cc = cv[2], cd = cv[3], ce = cv[4], cf = cv[5];
    float col[24] = {ca.x, ca.y, ca.z, ca.w, cb.x, cb.y, cb.z, cb.w,
                     cc.x, cc.y, cc.z, cc.w, cd.x, cd.y, cd.z, cd.w,
                     ce.x, ce.y, ce.z, ce.w, cf.x, cf.y, cf.z, cf.w};

    float r = 0.f, g = 0.f, bl = 0.f;
#pragma unroll
    for (int k = 0; k < 8; ++k) {
        int cnt = (i0 == k) + (i1 == k) + (i2 == k) + (i3 == k);
        float wk = __fmul_rn((float)cnt, 0.25f);
        r  = __fadd_rn(r,  __fmul_rn(wk, col[3 * k + 0]));
        g  = __fadd_rn(g,  __fmul_rn(wk, col[3 * k + 1]));
        bl = __fadd_rn(bl, __fmul_rn(wk, col[3 * k + 2]));
    }
    int cntb = (i0 == 8) + (i1 == 8) + (i2 == 8) + (i3 == 8);
    float wb = __fmul_rn((float)cntb, 0.25f);

    float4 o;
    o.x = __fadd_rn(r,  __fmul_rn(wb, bg[0]));
    o.y = __fadd_rn(g,  __fmul_rn(wb, bg[1]));
    o.z = __fadd_rn(bl, __fmul_rn(wb, bg[2]));
    o.w = 1.0f - alpha;
    *(float4*)(out + (size_t)pix * 4) = o;
}

// ---------------------------------------------------------------------------
// Host-side threefry for key derivation (full 2-word output).
// ---------------------------------------------------------------------------
static void threefry_host(uint32_t k0, uint32_t k1, uint32_t x0, uint32_t x1,
                          uint32_t* o0, uint32_t* o1)
{
    uint32_t k2 = k0 ^ k1 ^ 0x1BD11BDAu;
    x0 += k0; x1 += k1;
#define R(r) { x0 += x1; x1 = (x1 << (r)) | (x1 >> (32 - (r))); x1 ^= x0; }
    R(13) R(15) R(26) R(6)
    x0 += k1; x1 += k2 + 1u;
    R(17) R(29) R(16) R(24)
    x0 += k2; x1 += k0 + 2u;
    R(13) R(15) R(26) R(6)
    x0 += k0; x1 += k1 + 3u;
    R(17) R(29) R(16) R(24)
    x0 += k1; x1 += k2 + 4u;
    R(13) R(15) R(26) R(6)
    x0 += k2; x1 += k0 + 5u;
#undef R
    *o0 = x0; *o1 = x1;
}

extern "C" void kernel_launch(void* const* d_in, const int* in_sizes, int n_in,
                              void* d_out, int out_size)
{
    const float* colors = (const float*)d_in[0];
    const float* dists  = (const float*)d_in[1];
    const float* zbuf   = (const float*)d_in[2];
    const int*   p2f    = (const int*)  d_in[3];
    const float* bg     = (const float*)d_in[4];
    float*       out    = (float*)d_out;

    // jax.random.key(1) -> raw key (0, 1); partitionable split.
    uint32_t kh0, kh1, ka0, ka1;
    threefry_host(0u, 1u, 0u, 0u, &kh0, &kh1);   // kh = keys[0]
    threefry_host(0u, 1u, 0u, 1u, &ka0, &ka1);   // ka = keys[1]

    // log(EPS + prob) LUT, prob in {0, 0.25, 0.5, 0.75, 1.0}.
    float l0 = (float)log((double)1e-10f);
    float l1 = (float)log((double)(1e-10f + 0.25f));
    float l2 = (float)log((double)(1e-10f + 0.5f));
    float l3 = (float)log((double)(1e-10f + 0.75f));
    float l4 = (float)log((double)(1e-10f + 1.0f));

    dim3 grid((NPIX + 255) / 256);
    rps_kernel<<<grid, 256>>>(colors, dists, zbuf, p2f, bg, out,
                              kh0, kh1, ka0, ka1, l0, l1, l2, l3, l4, 1u);
}

// round 7
// speedup vs baseline: 1.0215x; 1.0215x over previous
#include <cuda_runtime.h>
#include <stdint.h>
#include <math.h>

// ---------------------------------------------------------------------------
// RandomPhongShader: N=8, H=256, W=256, K=8, NB_SAMPLES=4
// SIGMA=0.1, GAMMA=0.1, ZNEAR=1, ZFAR=100, EPS=1e-10
//
// JAX threefry PRNG, partitionable mode:
//   random_bits(32)[i] = out0 ^ out1 of threefry(key, hi=0, lo=i)
//
// Heaviside: integer-threshold fast path (decision-identical; rare exact
// fallback). Argmax: background entry pruned when provably unreachable
// (gap > 1.25 > 2*max|0.1*noise|); guard taken w.p. ~2e-10.
// Threefry adds left as plain '+': ptxas's own IADD3/IMAD pipe split is
// latency-optimal (forcing IMAD adds cross-pipe +1cyc per chain hop; R6).
// ---------------------------------------------------------------------------

#define NPIX (8 * 256 * 256)          // 524288 pixels
#define STRIDE_H 4194304u             // N*H*W*K     (per-sample stride, noise_h)
#define STRIDE_A 4718592u             // N*H*W*(K+1) (per-sample stride, noise_a)

// Full Threefry-2x32 with x0 = 0 (hi), x1 = ctr (lo); returns out0 ^ out1.
__device__ __forceinline__ uint32_t tf_xor(uint32_t k0, uint32_t k1, uint32_t ctr)
{
    uint32_t k2 = k0 ^ k1 ^ 0x1BD11BDAu;
    uint32_t x0 = k0;          // 0 + k0
    uint32_t x1 = ctr + k1;
#define TFR(r) { x0 += x1; x1 = __funnelshift_l(x1, x1, (r)); x1 ^= x0; }
    TFR(13) TFR(15) TFR(26) TFR(6)
    x0 += k1; x1 += k2 + 1u;
    TFR(17) TFR(29) TFR(16) TFR(24)
    x0 += k2; x1 += k0 + 2u;
    TFR(13) TFR(15) TFR(26) TFR(6)
    x0 += k0; x1 += k1 + 3u;
    TFR(17) TFR(29) TFR(16) TFR(24)
    x0 += k1; x1 += k2 + 4u;
    TFR(13) TFR(15) TFR(26) TFR(6)
    x0 += k2; x1 += k0 + 5u;
#undef TFR
    return x0 ^ x1;
}

// Giles erf_inv (same coefficients as XLA), FMA form + MUFU log.
__device__ __forceinline__ float erfinv_fast(float x)
{
    float t = __fmaf_rn(-x, x, 1.0f);          // 1 - x*x
    float w = -__logf(t);                      // MUFU LG2 * ln2
    float p;
    if (w < 5.0f) {
        w = w - 2.5f;
        p = 2.81022636e-08f;
        p = __fmaf_rn(p, w, 3.43273939e-07f);
        p = __fmaf_rn(p, w, -3.5233877e-06f);
        p = __fmaf_rn(p, w, -4.39150654e-06f);
        p = __fmaf_rn(p, w, 0.00021858087f);
        p = __fmaf_rn(p, w, -0.00125372503f);
        p = __fmaf_rn(p, w, -0.00417768164f);
        p = __fmaf_rn(p, w, 0.246640727f);
        p = __fmaf_rn(p, w, 1.50140941f);
    } else {
        w = sqrtf(w) - 3.0f;
        p = -0.000200214257f;
        p = __fmaf_rn(p, w, 0.000100950558f);
        p = __fmaf_rn(p, w, 0.00134934322f);
        p = __fmaf_rn(p, w, -0.00367342844f);
        p = __fmaf_rn(p, w, 0.00573950773f);
        p = __fmaf_rn(p, w, -0.0076224613f);
        p = __fmaf_rn(p, w, 0.00943887047f);
        p = __fmaf_rn(p, w, 1.00167406f);
        p = __fmaf_rn(p, w, 2.83297682f);
    }
    return p * x;
}

// m = bits>>9 -> N(0,1); exact same fp sequence as the reference mapping.
__device__ __forceinline__ float m_to_normal(uint32_t m)
{
    const float LO    = __uint_as_float(0xBF7FFFFFu);  // nextafter(-1, 0)
    const float SQRT2 = __uint_as_float(0x3FB504F3u);  // float32(sqrt(2))
    float u = __fmaf_rn((float)m, 0x1.0p-22f, LO);     // exact prod, 1 rounding
    return SQRT2 * erfinv_fast(u);
}

// Abramowitz-Stegun 7.1.26 erf, |abs err| <= ~1.5e-7 (plus expf/div ~1e-7).
__device__ __forceinline__ float erf_approx(float z)
{
    float az = fminf(fabsf(z), 4.0f);      // erf(4) = 1 - 1.5e-8, saturate
    float t  = __fdividef(1.0f, __fmaf_rn(0.3275911f, az, 1.0f));
    float y  = 1.061405429f;
    y = __fmaf_rn(y, t, -1.453152027f);
    y = __fmaf_rn(y, t,  1.421413741f);
    y = __fmaf_rn(y, t, -0.284496736f);
    y = __fmaf_rn(y, t,  0.254829592f);
    y = y * t;
    float e = __expf(-az * az);
    float r = __fmaf_rn(-y, e, 1.0f);
    return (z < 0.0f) ? -r : r;
}

__global__ void __launch_bounds__(256, 6)
rps_kernel(const float* __restrict__ colors,   // (N,H,W,K,3)
           const float* __restrict__ dists,    // (N,H,W,K)
           const float* __restrict__ zbuf,     // (N,H,W,K)
           const int*   __restrict__ p2f,      // (N,H,W,K)
           const float* __restrict__ bg,       // (3,)
           float*       __restrict__ out,      // (N,H,W,4)
           uint32_t kh0, uint32_t kh1, uint32_t ka0, uint32_t ka1,
           float l0, float l1, float l2, float l3, float l4)
{
    unsigned pix = blockIdx.x * 256u + threadIdx.x;
    if (pix >= NPIX) return;

    // ---- loads (vectorized) ----
    const float4* dv = (const float4*)(dists + (size_t)pix * 8);
    const float4* zv = (const float4*)(zbuf  + (size_t)pix * 8);
    const int4*   fv = (const int4*)  (p2f   + (size_t)pix * 8);
    float4 d0 = dv[0], d1 = dv[1];
    float4 z0 = zv[0], z1 = zv[1];
    int4   f0 = fv[0], f1 = fv[1];

    float dd[8] = {d0.x, d0.y, d0.z, d0.w, d1.x, d1.y, d1.z, d1.w};
    float zz[8] = {z0.x, z0.y, z0.z, z0.w, z1.x, z1.y, z1.z, z1.w};
    int   ff[8] = {f0.x, f0.y, f0.z, f0.w, f1.x, f1.y, f1.z, f1.w};

    // ---- heaviside via integer threshold / prob / alpha / z_inv / log-LUT --
    float logp[8], zinv[8];
    float alpha = 1.0f;
    uint32_t bh = pix * 8u;
#pragma unroll
    for (int k = 0; k < 8; ++k) {
        bool msk = (ff[k] >= 0);
        float mask = msk ? 1.0f : 0.0f;
        uint32_t b = bh + (uint32_t)k;
        float d = dd[k];
        float x = -d;

        // threshold on m = bits>>9: decision is (m >= m*), |m* - mth| << 64
        float uth = erf_approx(d * 7.0710678f);                 // erf(10d/sqrt2)
        // (uth - LO)*2^22 ; -LO*2^22 = (1-2^-24)*2^22 = 4194303.75 exactly
        int mth = __float2int_rn(__fmaf_rn(uth, 4194304.0f, 4194303.75f));
        int mhi = mth + 64;
        int mlo = mth - 64;

        int cnt = 0;
#pragma unroll
        for (int s = 0; s < 4; ++s) {
            uint32_t bits = tf_xor(kh0, kh1, b + (uint32_t)s * STRIDE_H);
            int m = (int)(bits >> 9);
            if (m >= mhi) {
                cnt++;
            } else if (m > mlo) {   // rare exact fallback (~3e-5 per sample)
                cnt += (__fadd_rn(x, __fmul_rn(0.1f, m_to_normal((uint32_t)m))) >= 0.0f);
            }
        }

        int idx = msk ? cnt : 0;
        float prob = __fmul_rn((float)cnt * 0.25f, mask);   // exact
        alpha = __fmul_rn(alpha, 1.0f - prob);              // exact product
        // log(EPS + prob): prob in {0,.25,.5,.75,1} -> 5-entry select
        float lv = l0;
        lv = (idx == 1) ? l1 : lv;
        lv = (idx == 2) ? l2 : lv;
        lv = (idx == 3) ? l3 : lv;
        lv = (idx == 4) ? l4 : lv;
        logp[k] = lv;
        zinv[k] = __fmul_rn(__fdiv_rn(__fsub_rn(100.0f, zz[k]), 99.0f), mask);
    }

    // ---- z_inv_max (clipped at EPS) ----
    float m = zinv[0];
#pragma unroll
    for (int k = 1; k < 8; ++k) m = fmaxf(m, zinv[k]);
    m = fmaxf(m, 1e-10f);

    // ---- z_map (9 entries incl. background score) ----
    float zm[9];
    float maxzm = -1e30f;
#pragma unroll
    for (int k = 0; k < 8; ++k) {
        zm[k] = __fadd_rn(logp[k], __fdiv_rn(__fsub_rn(zinv[k], m), 0.1f));
        maxzm = fmaxf(maxzm, zm[k]);
    }
    zm[8] = __fdiv_rn(__fsub_rn(1e-10f, m), 0.1f);

    // ---- random argmax: faces j=0..7 (4 samples each, first-max-wins) ----
    float b0 = 0.f, b1 = 0.f, b2 = 0.f, b3 = 0.f;
    int   i0 = 0, i1 = 0, i2 = 0, i3 = 0;
    uint32_t ba = pix * 9u;
#pragma unroll
    for (int j = 0; j < 8; ++j) {
        uint32_t c = ba + (uint32_t)j;
        float s0 = __fadd_rn(zm[j], __fmul_rn(0.1f, m_to_normal(tf_xor(ka0, ka1, c) >> 9)));
        float s1 = __fadd_rn(zm[j], __fmul_rn(0.1f, m_to_normal(tf_xor(ka0, ka1, c + STRIDE_A) >> 9)));
        float s2 = __fadd_rn(zm[j], __fmul_rn(0.1f, m_to_normal(tf_xor(ka0, ka1, c + 2u * STRIDE_A) >> 9)));
        float s3 = __fadd_rn(zm[j], __fmul_rn(0.1f, m_to_normal(tf_xor(ka0, ka1, c + 3u * STRIDE_A) >> 9)));
        if (j == 0) {
            b0 = s0; b1 = s1; b2 = s2; b3 = s3;
        } else {
            if (s0 > b0) { b0 = s0; i0 = j; }
            if (s1 > b1) { b1 = s1; i1 = j; }
            if (s2 > b2) { b2 = s2; i2 = j; }
            if (s3 > b3) { b3 = s3; i3 = j; }
        }
    }
    // Background (j=8): |0.1*noise| <= 0.543; if zm[8] is out of reach of the
    // best face score it can never win -> skip (taken w.p. ~2e-10).
    if (zm[8] > maxzm - 1.25f) {
        uint32_t c = ba + 8u;
        float s0 = __fadd_rn(zm[8], __fmul_rn(0.1f, m_to_normal(tf_xor(ka0, ka1, c) >> 9)));
        float s1 = __fadd_rn(zm[8], __fmul_rn(0.1f, m_to_normal(tf_xor(ka0, ka1, c + STRIDE_A) >> 9)));
        float s2 = __fadd_rn(zm[8], __fmul_rn(0.1f, m_to_normal(tf_xor(ka0, ka1, c + 2u * STRIDE_A) >> 9)));
        float s3 = __fadd_rn(zm[8], __fmul_rn(0.1f, m_to_normal(tf_xor(ka0, ka1, c + 3u * STRIDE_A) >> 9)));
        if (s0 > b0) { i0 = 8; }
        if (s1 > b1) { i1 = 8; }
        if (s2 > b2) { i2 = 8; }
        if (s3 > b3) { i3 = 8; }
    }

    // ---- weighted colors ----
    const float4* cv = (const float4*)(colors + (size_t)pix * 24);
    float4 ca = cv[0], cb = cv[1], cc = cv[2], cd = cv[3], ce = cv[4], cf = cv[5];
    float col[24] = {ca.x, ca.y, ca.z, ca.w, cb.x, cb.y, cb.z, cb.w,
                     cc.x, cc.y, cc.z, cc.w, cd.x, cd.y, cd.z, cd.w,
                     ce.x, ce.y, ce.z, ce.w, cf.x, cf.y, cf.z, cf.w};

    float r = 0.f, g = 0.f, bl = 0.f;
#pragma unroll
    for (int k = 0; k < 8; ++k) {
        int cnt = (i0 == k) + (i1 == k) + (i2 == k) + (i3 == k);
        float wk = __fmul_rn((float)cnt, 0.25f);
        r  = __fadd_rn(r,  __fmul_rn(wk, col[3 * k + 0]));
        g  = __fadd_rn(g,  __fmul_rn(wk, col[3 * k + 1]));
        bl = __fadd_rn(bl, __fmul_rn(wk, col[3 * k + 2]));
    }
    int cntb = (i0 == 8) + (i1 == 8) + (i2 == 8) + (i3 == 8);
    float wb = __fmul_rn((float)cntb, 0.25f);

    float4 o;
    o.x = __fadd_rn(r,  __fmul_rn(wb, bg[0]));
    o.y = __fadd_rn(g,  __fmul_rn(wb, bg[1]));
    o.z = __fadd_rn(bl, __fmul_rn(wb, bg[2]));
    o.w = 1.0f - alpha;
    *(float4*)(out + (size_t)pix * 4) = o;
}

// ---------------------------------------------------------------------------
// Host-side threefry for key derivation (full 2-word output).
// ---------------------------------------------------------------------------
static void threefry_host(uint32_t k0, uint32_t k1, uint32_t x0, uint32_t x1,
                          uint32_t* o0, uint32_t* o1)
{
    uint32_t k2 = k0 ^ k1 ^ 0x1BD11BDAu;
    x0 += k0; x1 += k1;
#define R(r) { x0 += x1; x1 = (x1 << (r)) | (x1 >> (32 - (r))); x1 ^= x0; }
    R(13) R(15) R(26) R(6)
    x0 += k1; x1 += k2 + 1u;
    R(17) R(29) R(16) R(24)
    x0 += k2; x1 += k0 + 2u;
    R(13) R(15) R(26) R(6)
    x0 += k0; x1 += k1 + 3u;
    R(17) R(29) R(16) R(24)
    x0 += k1; x1 += k2 + 4u;
    R(13) R(15) R(26) R(6)
    x0 += k2; x1 += k0 + 5u;
#undef R
    *o0 = x0; *o1 = x1;
}

extern "C" void kernel_launch(void* const* d_in, const int* in_sizes, int n_in,
                              void* d_out, int out_size)
{
    const float* colors = (const float*)d_in[0];
    const float* dists  = (const float*)d_in[1];
    const float* zbuf   = (const float*)d_in[2];
    const int*   p2f    = (const int*)  d_in[3];
    const float* bg     = (const float*)d_in[4];
    float*       out    = (float*)d_out;

    // jax.random.key(1) -> raw key (0, 1); partitionable split.
    uint32_t kh0, kh1, ka0, ka1;
    threefry_host(0u, 1u, 0u, 0u, &kh0, &kh1);   // kh = keys[0]
    threefry_host(0u, 1u, 0u, 1u, &ka0, &ka1);   // ka = keys[1]

    // log(EPS + prob) LUT, prob in {0, 0.25, 0.5, 0.75, 1.0}.
    float l0 = (float)log((double)1e-10f);
    float l1 = (float)log((double)(1e-10f + 0.25f));
    float l2 = (float)log((double)(1e-10f + 0.5f));
    float l3 = (float)log((double)(1e-10f + 0.75f));
    float l4 = (float)log((double)(1e-10f + 1.0f));

    dim3 grid((NPIX + 255) / 256);
    rps_kernel<<<grid, 256>>>(colors, dists, zbuf, p2f, bg, out,
                              kh0, kh1, ka0, ka1, l0, l1, l2, l3, l4);
}

// round 8
// speedup vs baseline: 1.3140x; 1.2863x over previous
#include <cuda_runtime.h>
#include <stdint.h>
#include <math.h>

// ---------------------------------------------------------------------------
// RandomPhongShader: N=8, H=256, W=256, K=8, NB_SAMPLES=4
// SIGMA=0.1, GAMMA=0.1, ZNEAR=1, ZFAR=100, EPS=1e-10
//
// JAX threefry PRNG, partitionable mode:
//   random_bits(32)[i] = out0 ^ out1 of threefry(key, hi=0, lo=i)
//
// R8: code-size-driven restructure. Outer loops NOT unrolled (hot code
// ~90KB -> ~14KB, fits L1.5 I$); 4-sample inner unroll kept for ILP.
// zinv staged in smem (indexed by loop var), log-LUT indices packed 3b/face
// into one register. Heaviside exact-fallback is __noinline__ (rare).
// Warp-uniform argmax prune via __all_sync (margin 0.6 > max|0.1*noise| =
// 0.543) -> background entry skips its 4 threefry calls warp-uniformly.
// All decision math identical to R5/R7 -> rel_err canary 1.287565e-08.
// ---------------------------------------------------------------------------

#define NPIX (8 * 256 * 256)          // 524288 pixels
#define STRIDE_H 4194304u             // N*H*W*K     (per-sample stride, noise_h)
#define STRIDE_A 4718592u             // N*H*W*(K+1) (per-sample stride, noise_a)

// Full Threefry-2x32 with x0 = 0 (hi), x1 = ctr (lo); returns out0 ^ out1.
__device__ __forceinline__ uint32_t tf_xor(uint32_t k0, uint32_t k1, uint32_t ctr)
{
    uint32_t k2 = k0 ^ k1 ^ 0x1BD11BDAu;
    uint32_t x0 = k0;          // 0 + k0
    uint32_t x1 = ctr + k1;
#define TFR(r) { x0 += x1; x1 = __funnelshift_l(x1, x1, (r)); x1 ^= x0; }
    TFR(13) TFR(15) TFR(26) TFR(6)
    x0 += k1; x1 += k2 + 1u;
    TFR(17) TFR(29) TFR(16) TFR(24)
    x0 += k2; x1 += k0 + 2u;
    TFR(13) TFR(15) TFR(26) TFR(6)
    x0 += k0; x1 += k1 + 3u;
    TFR(17) TFR(29) TFR(16) TFR(24)
    x0 += k1; x1 += k2 + 4u;
    TFR(13) TFR(15) TFR(26) TFR(6)
    x0 += k2; x1 += k0 + 5u;
#undef TFR
    return x0 ^ x1;
}

// Giles erf_inv (same coefficients as XLA), FMA form + MUFU log.
__device__ __forceinline__ float erfinv_fast(float x)
{
    float t = __fmaf_rn(-x, x, 1.0f);          // 1 - x*x
    float w = -__logf(t);                      // MUFU LG2 * ln2
    float p;
    if (w < 5.0f) {
        w = w - 2.5f;
        p = 2.81022636e-08f;
        p = __fmaf_rn(p, w, 3.43273939e-07f);
        p = __fmaf_rn(p, w, -3.5233877e-06f);
        p = __fmaf_rn(p, w, -4.39150654e-06f);
        p = __fmaf_rn(p, w, 0.00021858087f);
        p = __fmaf_rn(p, w, -0.00125372503f);
        p = __fmaf_rn(p, w, -0.00417768164f);
        p = __fmaf_rn(p, w, 0.246640727f);
        p = __fmaf_rn(p, w, 1.50140941f);
    } else {
        w = sqrtf(w) - 3.0f;
        p = -0.000200214257f;
        p = __fmaf_rn(p, w, 0.000100950558f);
        p = __fmaf_rn(p, w, 0.00134934322f);
        p = __fmaf_rn(p, w, -0.00367342844f);
        p = __fmaf_rn(p, w, 0.00573950773f);
        p = __fmaf_rn(p, w, -0.0076224613f);
        p = __fmaf_rn(p, w, 0.00943887047f);
        p = __fmaf_rn(p, w, 1.00167406f);
        p = __fmaf_rn(p, w, 2.83297682f);
    }
    return p * x;
}

// m = bits>>9 -> N(0,1); exact same fp sequence as the reference mapping.
__device__ __forceinline__ float m_to_normal(uint32_t m)
{
    const float LO    = __uint_as_float(0xBF7FFFFFu);  // nextafter(-1, 0)
    const float SQRT2 = __uint_as_float(0x3FB504F3u);  // float32(sqrt(2))
    float u = __fmaf_rn((float)m, 0x1.0p-22f, LO);     // exact prod, 1 rounding
    return SQRT2 * erfinv_fast(u);
}

// Rare exact heaviside fallback; out of line to keep the hot path small.
__device__ __noinline__ int heaviside_exact(float x, uint32_t m)
{
    return (__fadd_rn(x, __fmul_rn(0.1f, m_to_normal(m))) >= 0.0f) ? 1 : 0;
}

// Abramowitz-Stegun 7.1.26 erf, |abs err| <= ~1.5e-7 (plus expf/div ~1e-7).
__device__ __forceinline__ float erf_approx(float z)
{
    float az = fminf(fabsf(z), 4.0f);      // erf(4) = 1 - 1.5e-8, saturate
    float t  = __fdividef(1.0f, __fmaf_rn(0.3275911f, az, 1.0f));
    float y  = 1.061405429f;
    y = __fmaf_rn(y, t, -1.453152027f);
    y = __fmaf_rn(y, t,  1.421413741f);
    y = __fmaf_rn(y, t, -0.284496736f);
    y = __fmaf_rn(y, t,  0.254829592f);
    y = y * t;
    float e = __expf(-az * az);
    float r = __fmaf_rn(-y, e, 1.0f);
    return (z < 0.0f) ? -r : r;
}

__global__ void __launch_bounds__(256, 6)
rps_kernel(const float* __restrict__ colors,   // (N,H,W,K,3)
           const float* __restrict__ dists,    // (N,H,W,K)
           const float* __restrict__ zbuf,     // (N,H,W,K)
           const int*   __restrict__ p2f,      // (N,H,W,K)
           const float* __restrict__ bg,       // (3,)
           float*       __restrict__ out,      // (N,H,W,4)
           uint32_t kh0, uint32_t kh1, uint32_t ka0, uint32_t ka1,
           float l0, float l1, float l2, float l3, float l4)
{
    __shared__ float zinv_s[8 * 256];

    unsigned tid = threadIdx.x;
    unsigned pix = blockIdx.x * 256u + tid;
    if (pix >= NPIX) return;

    const float* dp = dists + (size_t)pix * 8;
    const float* zp = zbuf  + (size_t)pix * 8;
    const int*   fp = p2f   + (size_t)pix * 8;

    // ---- phase 1: heaviside via integer threshold; alpha; zinv; idx pack ---
    float alpha = 1.0f;
    float zmax  = -1e30f;
    uint32_t idxpack = 0;
    uint32_t bh = pix * 8u;

#pragma unroll 1
    for (int k = 0; k < 8; ++k) {
        float d = __ldg(dp + k);
        float z = __ldg(zp + k);
        int   f = __ldg(fp + k);
        bool msk = (f >= 0);
        float mask = msk ? 1.0f : 0.0f;
        uint32_t b = bh + (uint32_t)k;
        float x = -d;

        // threshold on m = bits>>9: decision is (m >= m*), |m* - mth| << 64
        float uth = erf_approx(d * 7.0710678f);                 // erf(10d/sqrt2)
        // (uth - LO)*2^22 ; -LO*2^22 = (1-2^-24)*2^22 = 4194303.75 exactly
        int mth = __float2int_rn(__fmaf_rn(uth, 4194304.0f, 4194303.75f));
        int mhi = mth + 64;
        int mlo = mth - 64;

        int cnt = 0;
#pragma unroll
        for (int s = 0; s < 4; ++s) {
            uint32_t bits = tf_xor(kh0, kh1, b + (uint32_t)s * STRIDE_H);
            int m = (int)(bits >> 9);
            if (m >= mhi) {
                cnt++;
            } else if (m > mlo) {   // rare exact fallback (~3e-5 per sample)
                cnt += heaviside_exact(x, (uint32_t)m);
            }
        }

        int idx = msk ? cnt : 0;
        float prob = __fmul_rn((float)cnt * 0.25f, mask);   // exact
        alpha = __fmul_rn(alpha, 1.0f - prob);              // exact product
        float zinvk = __fmul_rn(__fdiv_rn(__fsub_rn(100.0f, z), 99.0f), mask);
        zmax = fmaxf(zmax, zinvk);
        zinv_s[k * 256 + tid] = zinvk;
        idxpack |= (uint32_t)idx << (3 * k);
    }
    zmax = fmaxf(zmax, 1e-10f);

    // ---- phase 2: random argmax over 9 entries, 4 samples, first-max-wins --
    float b0 = -1e30f, b1 = -1e30f, b2 = -1e30f, b3 = -1e30f;
    int   i0 = 0, i1 = 0, i2 = 0, i3 = 0;
    uint32_t ba = pix * 9u;

#pragma unroll 1
    for (int j = 0; j < 9; ++j) {
        float zmj;
        if (j < 8) {
            float zinvj = zinv_s[j * 256 + tid];
            uint32_t idx = (idxpack >> (3 * j)) & 7u;
            float lv = l0;
            lv = (idx == 1) ? l1 : lv;
            lv = (idx == 2) ? l2 : lv;
            lv = (idx == 3) ? l3 : lv;
            lv = (idx == 4) ? l4 : lv;
            zmj = __fadd_rn(lv, __fdiv_rn(__fsub_rn(zinvj, zmax), 0.1f));
        } else {
            zmj = __fdiv_rn(__fsub_rn(1e-10f, zmax), 0.1f);
        }

        // Warp-uniform prune: max |0.1*noise| = 0.543 < 0.6; entry j can't
        // beat any current best in any lane -> skip its 4 threefry evals.
        float bmin = fminf(fminf(b0, b1), fminf(b2, b3));
        bool cant_win = (zmj < bmin - 0.6f);
        if (__all_sync(0xFFFFFFFFu, cant_win)) continue;

        uint32_t c = ba + (uint32_t)j;
        float s0 = __fadd_rn(zmj, __fmul_rn(0.1f, m_to_normal(tf_xor(ka0, ka1, c) >> 9)));
        float s1 = __fadd_rn(zmj, __fmul_rn(0.1f, m_to_normal(tf_xor(ka0, ka1, c + STRIDE_A) >> 9)));
        float s2 = __fadd_rn(zmj, __fmul_rn(0.1f, m_to_normal(tf_xor(ka0, ka1, c + 2u * STRIDE_A) >> 9)));
        float s3 = __fadd_rn(zmj, __fmul_rn(0.1f, m_to_normal(tf_xor(ka0, ka1, c + 3u * STRIDE_A) >> 9)));
        if (s0 > b0) { b0 = s0; i0 = j; }
        if (s1 > b1) { b1 = s1; i1 = j; }
        if (s2 > b2) { b2 = s2; i2 = j; }
        if (s3 > b3) { b3 = s3; i3 = j; }
    }

    // ---- phase 3: weighted colors (reference summation order k=0..7) ------
    const float* cp = colors + (size_t)pix * 24;
    float r = 0.f, g = 0.f, bl = 0.f;
#pragma unroll 1
    for (int k = 0; k < 8; ++k) {
        int cnt = (i0 == k) + (i1 == k) + (i2 == k) + (i3 == k);
        if (cnt) {
            float wk = __fmul_rn((float)cnt, 0.25f);
            r  = __fadd_rn(r,  __fmul_rn(wk, __ldg(cp + 3 * k + 0)));
            g  = __fadd_rn(g,  __fmul_rn(wk, __ldg(cp + 3 * k + 1)));
            bl = __fadd_rn(bl, __fmul_rn(wk, __ldg(cp + 3 * k + 2)));
        }
    }
    int cntb = (i0 == 8) + (i1 == 8) + (i2 == 8) + (i3 == 8);
    float wb = __fmul_rn((float)cntb, 0.25f);

    float4 o;
    o.x = __fadd_rn(r,  __fmul_rn(wb, bg[0]));
    o.y = __fadd_rn(g,  __fmul_rn(wb, bg[1]));
    o.z = __fadd_rn(bl, __fmul_rn(wb, bg[2]));
    o.w = 1.0f - alpha;
    *(float4*)(out + (size_t)pix * 4) = o;
}

// ---------------------------------------------------------------------------
// Host-side threefry for key derivation (full 2-word output).
// ---------------------------------------------------------------------------
static void threefry_host(uint32_t k0, uint32_t k1, uint32_t x0, uint32_t x1,
                          uint32_t* o0, uint32_t* o1)
{
    uint32_t k2 = k0 ^ k1 ^ 0x1BD11BDAu;
    x0 += k0; x1 += k1;
#define R(r) { x0 += x1; x1 = (x1 << (r)) | (x1 >> (32 - (r))); x1 ^= x0; }
    R(13) R(15) R(26) R(6)
    x0 += k1; x1 += k2 + 1u;
    R(17) R(29) R(16) R(24)
    x0 += k2; x1 += k0 + 2u;
    R(13) R(15) R(26) R(6)
    x0 += k0; x1 += k1 + 3u;
    R(17) R(29) R(16) R(24)
    x0 += k1; x1 += k2 + 4u;
    R(13) R(15) R(26) R(6)
    x0 += k2; x1 += k0 + 5u;
#undef R
    *o0 = x0; *o1 = x1;
}

extern "C" void kernel_launch(void* const* d_in, const int* in_sizes, int n_in,
                              void* d_out, int out_size)
{
    const float* colors = (const float*)d_in[0];
    const float* dists  = (const float*)d_in[1];
    const float* zbuf   = (const float*)d_in[2];
    const int*   p2f    = (const int*)  d_in[3];
    const float* bg     = (const float*)d_in[4];
    float*       out    = (float*)d_out;

    // jax.random.key(1) -> raw key (0, 1); partitionable split.
    uint32_t kh0, kh1, ka0, ka1;
    threefry_host(0u, 1u, 0u, 0u, &kh0, &kh1);   // kh = keys[0]
    threefry_host(0u, 1u, 0u, 1u, &ka0, &ka1);   // ka = keys[1]

    // log(EPS + prob) LUT, prob in {0, 0.25, 0.5, 0.75, 1.0}.
    float l0 = (float)log((double)1e-10f);
    float l1 = (float)log((double)(1e-10f + 0.25f));
    float l2 = (float)log((double)(1e-10f + 0.5f));
    float l3 = (float)log((double)(1e-10f + 0.75f));
    float l4 = (float)log((double)(1e-10f + 1.0f));

    dim3 grid((NPIX + 255) / 256);
    rps_kernel<<<grid, 256>>>(colors, dists, zbuf, p2f, bg, out,
                              kh0, kh1, ka0, ka1, l0, l1, l2, l3, l4);
}

// round 9
// speedup vs baseline: 1.3557x; 1.0317x over previous
#include <cuda_runtime.h>
#include <stdint.h>
#include <math.h>

// ---------------------------------------------------------------------------
// RandomPhongShader: N=8, H=256, W=256, K=8, NB_SAMPLES=4
// SIGMA=0.1, GAMMA=0.1, ZNEAR=1, ZFAR=100, EPS=1e-10
//
// JAX threefry PRNG, partitionable mode:
//   random_bits(32)[i] = out0 ^ out1 of threefry(key, hi=0, lo=i)
//
// R9: overhead strip. No warp votes (face prune never fires; bg prune is a
// per-lane branch with margin 0.6 > max|0.1*noise|=0.543 -> taken ~never).
// log-LUT via 5-word smem table (same-word broadcast, conflict-free LDS)
// instead of 4-SEL chains. Unconditional float4 color loads (no BSSY).
// Argmax loop unroll 2 (~22KB hot code, fits 32KB L1.5 I$).
// Decision math identical -> rel_err canary 1.287565e-08.
// ---------------------------------------------------------------------------

#define NPIX (8 * 256 * 256)          // 524288 pixels
#define STRIDE_H 4194304u             // N*H*W*K     (per-sample stride, noise_h)
#define STRIDE_A 4718592u             // N*H*W*(K+1) (per-sample stride, noise_a)

// Full Threefry-2x32 with x0 = 0 (hi), x1 = ctr (lo); returns out0 ^ out1.
__device__ __forceinline__ uint32_t tf_xor(uint32_t k0, uint32_t k1, uint32_t ctr)
{
    uint32_t k2 = k0 ^ k1 ^ 0x1BD11BDAu;
    uint32_t x0 = k0;          // 0 + k0
    uint32_t x1 = ctr + k1;
#define TFR(r) { x0 += x1; x1 = __funnelshift_l(x1, x1, (r)); x1 ^= x0; }
    TFR(13) TFR(15) TFR(26) TFR(6)
    x0 += k1; x1 += k2 + 1u;
    TFR(17) TFR(29) TFR(16) TFR(24)
    x0 += k2; x1 += k0 + 2u;
    TFR(13) TFR(15) TFR(26) TFR(6)
    x0 += k0; x1 += k1 + 3u;
    TFR(17) TFR(29) TFR(16) TFR(24)
    x0 += k1; x1 += k2 + 4u;
    TFR(13) TFR(15) TFR(26) TFR(6)
    x0 += k2; x1 += k0 + 5u;
#undef TFR
    return x0 ^ x1;
}

// Giles erf_inv (same coefficients as XLA), FMA form + MUFU log.
__device__ __forceinline__ float erfinv_fast(float x)
{
    float t = __fmaf_rn(-x, x, 1.0f);          // 1 - x*x
    float w = -__logf(t);                      // MUFU LG2 * ln2
    float p;
    if (w < 5.0f) {
        w = w - 2.5f;
        p = 2.81022636e-08f;
        p = __fmaf_rn(p, w, 3.43273939e-07f);
        p = __fmaf_rn(p, w, -3.5233877e-06f);
        p = __fmaf_rn(p, w, -4.39150654e-06f);
        p = __fmaf_rn(p, w, 0.00021858087f);
        p = __fmaf_rn(p, w, -0.00125372503f);
        p = __fmaf_rn(p, w, -0.00417768164f);
        p = __fmaf_rn(p, w, 0.246640727f);
        p = __fmaf_rn(p, w, 1.50140941f);
    } else {
        w = sqrtf(w) - 3.0f;
        p = -0.000200214257f;
        p = __fmaf_rn(p, w, 0.000100950558f);
        p = __fmaf_rn(p, w, 0.00134934322f);
        p = __fmaf_rn(p, w, -0.00367342844f);
        p = __fmaf_rn(p, w, 0.00573950773f);
        p = __fmaf_rn(p, w, -0.0076224613f);
        p = __fmaf_rn(p, w, 0.00943887047f);
        p = __fmaf_rn(p, w, 1.00167406f);
        p = __fmaf_rn(p, w, 2.83297682f);
    }
    return p * x;
}

// m = bits>>9 -> N(0,1); exact same fp sequence as the reference mapping.
__device__ __forceinline__ float m_to_normal(uint32_t m)
{
    const float LO    = __uint_as_float(0xBF7FFFFFu);  // nextafter(-1, 0)
    const float SQRT2 = __uint_as_float(0x3FB504F3u);  // float32(sqrt(2))
    float u = __fmaf_rn((float)m, 0x1.0p-22f, LO);     // exact prod, 1 rounding
    return SQRT2 * erfinv_fast(u);
}

// Rare exact heaviside fallback; out of line to keep the hot path small.
__device__ __noinline__ int heaviside_exact(float x, uint32_t m)
{
    return (__fadd_rn(x, __fmul_rn(0.1f, m_to_normal(m))) >= 0.0f) ? 1 : 0;
}

// Abramowitz-Stegun 7.1.26 erf, |abs err| <= ~1.5e-7 (plus expf/div ~1e-7).
__device__ __forceinline__ float erf_approx(float z)
{
    float az = fminf(fabsf(z), 4.0f);      // erf(4) = 1 - 1.5e-8, saturate
    float t  = __fdividef(1.0f, __fmaf_rn(0.3275911f, az, 1.0f));
    float y  = 1.061405429f;
    y = __fmaf_rn(y, t, -1.453152027f);
    y = __fmaf_rn(y, t,  1.421413741f);
    y = __fmaf_rn(y, t, -0.284496736f);
    y = __fmaf_rn(y, t,  0.254829592f);
    y = y * t;
    float e = __expf(-az * az);
    float r = __fmaf_rn(-y, e, 1.0f);
    return (z < 0.0f) ? -r : r;
}

__global__ void __launch_bounds__(256, 6)
rps_kernel(const float* __restrict__ colors,   // (N,H,W,K,3)
           const float* __restrict__ dists,    // (N,H,W,K)
           const float* __restrict__ zbuf,     // (N,H,W,K)
           const int*   __restrict__ p2f,      // (N,H,W,K)
           const float* __restrict__ bg,       // (3,)
           float*       __restrict__ out,      // (N,H,W,4)
           uint32_t kh0, uint32_t kh1, uint32_t ka0, uint32_t ka1,
           float l0, float l1, float l2, float l3, float l4)
{
    __shared__ float zinv_s[8 * 256];
    __shared__ float lut_s[5];

    unsigned tid = threadIdx.x;
    unsigned pix = blockIdx.x * 256u + tid;   // grid is exactly NPIX/256

    if (tid == 0) {
        lut_s[0] = l0; lut_s[1] = l1; lut_s[2] = l2; lut_s[3] = l3; lut_s[4] = l4;
    }
    __syncthreads();

    const float* dp = dists + (size_t)pix * 8;
    const float* zp = zbuf  + (size_t)pix * 8;
    const int*   fp = p2f   + (size_t)pix * 8;

    // ---- phase 1: heaviside via integer threshold; alpha; zinv; idx pack ---
    float alpha = 1.0f;
    float zmax  = -1e30f;
    uint32_t idxpack = 0;
    uint32_t bh = pix * 8u;

#pragma unroll 1
    for (int k = 0; k < 8; ++k) {
        float d = __ldg(dp + k);
        float z = __ldg(zp + k);
        int   f = __ldg(fp + k);
        bool msk = (f >= 0);
        float mask = msk ? 1.0f : 0.0f;
        uint32_t b = bh + (uint32_t)k;
        float x = -d;

        // threshold on m = bits>>9: decision is (m >= m*), |m* - mth| << 64
        float uth = erf_approx(d * 7.0710678f);                 // erf(10d/sqrt2)
        // (uth - LO)*2^22 ; -LO*2^22 = (1-2^-24)*2^22 = 4194303.75 exactly
        int mth = __float2int_rn(__fmaf_rn(uth, 4194304.0f, 4194303.75f));
        int mhi = mth + 64;
        int mlo = mth - 64;

        int cnt = 0;
#pragma unroll
        for (int s = 0; s < 4; ++s) {
            uint32_t bits = tf_xor(kh0, kh1, b + (uint32_t)s * STRIDE_H);
            int m = (int)(bits >> 9);
            if (m >= mhi) {
                cnt++;
            } else if (m > mlo) {   // rare exact fallback (~3e-5 per sample)
                cnt += heaviside_exact(x, (uint32_t)m);
            }
        }

        int idx = msk ? cnt : 0;
        float prob = __fmul_rn((float)cnt * 0.25f, mask);   // exact
        alpha = __fmul_rn(alpha, 1.0f - prob);              // exact product
        float zinvk = __fmul_rn(__fdiv_rn(__fsub_rn(100.0f, z), 99.0f), mask);
        zmax = fmaxf(zmax, zinvk);
        zinv_s[k * 256 + tid] = zinvk;
        idxpack |= (uint32_t)idx << (3 * k);
    }
    zmax = fmaxf(zmax, 1e-10f);

    // ---- phase 2: random argmax, faces j=0..7, 4 samples, first-max-wins ---
    float b0 = -1e30f, b1 = -1e30f, b2 = -1e30f, b3 = -1e30f;
    int   i0 = 0, i1 = 0, i2 = 0, i3 = 0;
    uint32_t ba = pix * 9u;

#pragma unroll 2
    for (int j = 0; j < 8; ++j) {
        float zinvj = zinv_s[j * 256 + tid];
        float lv = lut_s[(idxpack >> (3 * j)) & 7u];   // log(EPS+prob), broadcastable LDS
        float zmj = __fadd_rn(lv, __fdiv_rn(__fsub_rn(zinvj, zmax), 0.1f));

        uint32_t c = ba + (uint32_t)j;
        float s0 = __fadd_rn(zmj, __fmul_rn(0.1f, m_to_normal(tf_xor(ka0, ka1, c) >> 9)));
        float s1 = __fadd_rn(zmj, __fmul_rn(0.1f, m_to_normal(tf_xor(ka0, ka1, c + STRIDE_A) >> 9)));
        float s2 = __fadd_rn(zmj, __fmul_rn(0.1f, m_to_normal(tf_xor(ka0, ka1, c + 2u * STRIDE_A) >> 9)));
        float s3 = __fadd_rn(zmj, __fmul_rn(0.1f, m_to_normal(tf_xor(ka0, ka1, c + 3u * STRIDE_A) >> 9)));
        if (s0 > b0) { b0 = s0; i0 = j; }
        if (s1 > b1) { b1 = s1; i1 = j; }
        if (s2 > b2) { b2 = s2; i2 = j; }
        if (s3 > b3) { b3 = s3; i3 = j; }
    }
    // Background (j=8): max |0.1*noise| = 0.543 < 0.6; if zm8 can't reach the
    // weakest running best it can never win any sample -> skip (~never taken).
    {
        float zm8 = __fdiv_rn(__fsub_rn(1e-10f, zmax), 0.1f);
        float bmin = fminf(fminf(b0, b1), fminf(b2, b3));
        if (zm8 > bmin - 0.6f) {
            uint32_t c = ba + 8u;
            float s0 = __fadd_rn(zm8, __fmul_rn(0.1f, m_to_normal(tf_xor(ka0, ka1, c) >> 9)));
            float s1 = __fadd_rn(zm8, __fmul_rn(0.1f, m_to_normal(tf_xor(ka0, ka1, c + STRIDE_A) >> 9)));
            float s2 = __fadd_rn(zm8, __fmul_rn(0.1f, m_to_normal(tf_xor(ka0, ka1, c + 2u * STRIDE_A) >> 9)));
            float s3 = __fadd_rn(zm8, __fmul_rn(0.1f, m_to_normal(tf_xor(ka0, ka1, c + 3u * STRIDE_A) >> 9)));
            if (s0 > b0) { i0 = 8; }
            if (s1 > b1) { i1 = 8; }
            if (s2 > b2) { i2 = 8; }
            if (s3 > b3) { i3 = 8; }
        }
    }

    // ---- phase 3: weighted colors (reference summation order k=0..7) ------
    const float4* cv = (const float4*)(colors + (size_t)pix * 24);
    float4 ca = cv[0], cb = cv[1], cc = cv[2], cd = cv[3], ce = cv[4], cf = cv[5];
    float col[24] = {ca.x, ca.y, ca.z, ca.w, cb.x, cb.y, cb.z, cb.w,
                     cc.x, cc.y, cc.z, cc.w, cd.x, cd.y, cd.z, cd.w,
                     ce.x, ce.y, ce.z, ce.w, cf.x, cf.y, cf.z, cf.w};

    float r = 0.f, g = 0.f, bl = 0.f;
#pragma unroll
    for (int k = 0; k < 8; ++k) {
        int cnt = (i0 == k) + (i1 == k) + (i2 == k) + (i3 == k);
        float wk = __fmul_rn((float)cnt, 0.25f);
        r  = __fadd_rn(r,  __fmul_rn(wk, col[3 * k + 0]));
        g  = __fadd_rn(g,  __fmul_rn(wk, col[3 * k + 1]));
        bl = __fadd_rn(bl, __fmul_rn(wk, col[3 * k + 2]));
    }
    int cntb = (i0 == 8) + (i1 == 8) + (i2 == 8) + (i3 == 8);
    float wb = __fmul_rn((float)cntb, 0.25f);

    float4 o;
    o.x = __fadd_rn(r,  __fmul_rn(wb, bg[0]));
    o.y = __fadd_rn(g,  __fmul_rn(wb, bg[1]));
    o.z = __fadd_rn(bl, __fmul_rn(wb, bg[2]));
    o.w = 1.0f - alpha;
    *(float4*)(out + (size_t)pix * 4) = o;
}

// ---------------------------------------------------------------------------
// Host-side threefry for key derivation (full 2-word output).
// ---------------------------------------------------------------------------
static void threefry_host(uint32_t k0, uint32_t k1, uint32_t x0, uint32_t x1,
                          uint32_t* o0, uint32_t* o1)
{
    uint32_t k2 = k0 ^ k1 ^ 0x1BD11BDAu;
    x0 += k0; x1 += k1;
#define R(r) { x0 += x1; x1 = (x1 << (r)) | (x1 >> (32 - (r))); x1 ^= x0; }
    R(13) R(15) R(26) R(6)
    x0 += k1; x1 += k2 + 1u;
    R(17) R(29) R(16) R(24)
    x0 += k2; x1 += k0 + 2u;
    R(13) R(15) R(26) R(6)
    x0 += k0; x1 += k1 + 3u;
    R(17) R(29) R(16) R(24)
    x0 += k1; x1 += k2 + 4u;
    R(13) R(15) R(26) R(6)
    x0 += k2; x1 += k0 + 5u;
#undef R
    *o0 = x0; *o1 = x1;
}

extern "C" void kernel_launch(void* const* d_in, const int* in_sizes, int n_in,
                              void* d_out, int out_size)
{
    const float* colors = (const float*)d_in[0];
    const float* dists  = (const float*)d_in[1];
    const float* zbuf   = (const float*)d_in[2];
    const int*   p2f    = (const int*)  d_in[3];
    const float* bg     = (const float*)d_in[4];
    float*       out    = (float*)d_out;

    // jax.random.key(1) -> raw key (0, 1); partitionable split.
    uint32_t kh0, kh1, ka0, ka1;
    threefry_host(0u, 1u, 0u, 0u, &kh0, &kh1);   // kh = keys[0]
    threefry_host(0u, 1u, 0u, 1u, &ka0, &ka1);   // ka = keys[1]

    // log(EPS + prob) LUT, prob in {0, 0.25, 0.5, 0.75, 1.0}.
    float l0 = (float)log((double)1e-10f);
    float l1 = (float)log((double)(1e-10f + 0.25f));
    float l2 = (float)log((double)(1e-10f + 0.5f));
    float l3 = (float)log((double)(1e-10f + 0.75f));
    float l4 = (float)log((double)(1e-10f + 1.0f));

    dim3 grid(NPIX / 256);
    rps_kernel<<<grid, 256>>>(colors, dists, zbuf, p2f, bg, out,
                              kh0, kh1, ka0, ka1, l0, l1, l2, l3, l4);
}

// round 10
// speedup vs baseline: 1.3721x; 1.0121x over previous
#include <cuda_runtime.h>
#include <stdint.h>
#include <math.h>

// ---------------------------------------------------------------------------
// RandomPhongShader: N=8, H=256, W=256, K=8, NB_SAMPLES=4
// SIGMA=0.1, GAMMA=0.1, ZNEAR=1, ZFAR=100, EPS=1e-10
//
// JAX threefry PRNG, partitionable mode:
//   random_bits(32)[i] = out0 ^ out1 of threefry(key, hi=0, lo=i)
//
// R10: occupancy + ALU shave. __launch_bounds__(256,8) forces 32 regs ->
// up to 64 warps/SM (R8 proved no spills at 32). Phase 1 stores (zinv, logp)
// as float2 in smem (logp via 5-word LUT on the LSU pipe); phase 2 is one
// LDS.64 + 3 float ops per entry -- idxpack shifts/ands gone.
// Decision math identical -> rel_err canary 1.287565e-08.
// ---------------------------------------------------------------------------

#define NPIX (8 * 256 * 256)          // 524288 pixels
#define STRIDE_H 4194304u             // N*H*W*K     (per-sample stride, noise_h)
#define STRIDE_A 4718592u             // N*H*W*(K+1) (per-sample stride, noise_a)

// Full Threefry-2x32 with x0 = 0 (hi), x1 = ctr (lo); returns out0 ^ out1.
__device__ __forceinline__ uint32_t tf_xor(uint32_t k0, uint32_t k1, uint32_t ctr)
{
    uint32_t k2 = k0 ^ k1 ^ 0x1BD11BDAu;
    uint32_t x0 = k0;          // 0 + k0
    uint32_t x1 = ctr + k1;
#define TFR(r) { x0 += x1; x1 = __funnelshift_l(x1, x1, (r)); x1 ^= x0; }
    TFR(13) TFR(15) TFR(26) TFR(6)
    x0 += k1; x1 += k2 + 1u;
    TFR(17) TFR(29) TFR(16) TFR(24)
    x0 += k2; x1 += k0 + 2u;
    TFR(13) TFR(15) TFR(26) TFR(6)
    x0 += k0; x1 += k1 + 3u;
    TFR(17) TFR(29) TFR(16) TFR(24)
    x0 += k1; x1 += k2 + 4u;
    TFR(13) TFR(15) TFR(26) TFR(6)
    x0 += k2; x1 += k0 + 5u;
#undef TFR
    return x0 ^ x1;
}

// Giles erf_inv (same coefficients as XLA), FMA form + MUFU log.
__device__ __forceinline__ float erfinv_fast(float x)
{
    float t = __fmaf_rn(-x, x, 1.0f);          // 1 - x*x
    float w = -__logf(t);                      // MUFU LG2 * ln2
    float p;
    if (w < 5.0f) {
        w = w - 2.5f;
        p = 2.81022636e-08f;
        p = __fmaf_rn(p, w, 3.43273939e-07f);
        p = __fmaf_rn(p, w, -3.5233877e-06f);
        p = __fmaf_rn(p, w, -4.39150654e-06f);
        p = __fmaf_rn(p, w, 0.00021858087f);
        p = __fmaf_rn(p, w, -0.00125372503f);
        p = __fmaf_rn(p, w, -0.00417768164f);
        p = __fmaf_rn(p, w, 0.246640727f);
        p = __fmaf_rn(p, w, 1.50140941f);
    } else {
        w = sqrtf(w) - 3.0f;
        p = -0.000200214257f;
        p = __fmaf_rn(p, w, 0.000100950558f);
        p = __fmaf_rn(p, w, 0.00134934322f);
        p = __fmaf_rn(p, w, -0.00367342844f);
        p = __fmaf_rn(p, w, 0.00573950773f);
        p = __fmaf_rn(p, w, -0.0076224613f);
        p = __fmaf_rn(p, w, 0.00943887047f);
        p = __fmaf_rn(p, w, 1.00167406f);
        p = __fmaf_rn(p, w, 2.83297682f);
    }
    return p * x;
}

// m = bits>>9 -> N(0,1); exact same fp sequence as the reference mapping.
__device__ __forceinline__ float m_to_normal(uint32_t m)
{
    const float LO    = __uint_as_float(0xBF7FFFFFu);  // nextafter(-1, 0)
    const float SQRT2 = __uint_as_float(0x3FB504F3u);  // float32(sqrt(2))
    float u = __fmaf_rn((float)m, 0x1.0p-22f, LO);     // exact prod, 1 rounding
    return SQRT2 * erfinv_fast(u);
}

// Rare exact heaviside fallback; out of line to keep the hot path small.
__device__ __noinline__ int heaviside_exact(float x, uint32_t m)
{
    return (__fadd_rn(x, __fmul_rn(0.1f, m_to_normal(m))) >= 0.0f) ? 1 : 0;
}

// Abramowitz-Stegun 7.1.26 erf, |abs err| <= ~1.5e-7 (plus expf/div ~1e-7).
__device__ __forceinline__ float erf_approx(float z)
{
    float az = fminf(fabsf(z), 4.0f);      // erf(4) = 1 - 1.5e-8, saturate
    float t  = __fdividef(1.0f, __fmaf_rn(0.3275911f, az, 1.0f));
    float y  = 1.061405429f;
    y = __fmaf_rn(y, t, -1.453152027f);
    y = __fmaf_rn(y, t,  1.421413741f);
    y = __fmaf_rn(y, t, -0.284496736f);
    y = __fmaf_rn(y, t,  0.254829592f);
    y = y * t;
    float e = __expf(-az * az);
    float r = __fmaf_rn(-y, e, 1.0f);
    return (z < 0.0f) ? -r : r;
}

__global__ void __launch_bounds__(256, 8)
rps_kernel(const float* __restrict__ colors,   // (N,H,W,K,3)
           const float* __restrict__ dists,    // (N,H,W,K)
           const float* __restrict__ zbuf,     // (N,H,W,K)
           const int*   __restrict__ p2f,      // (N,H,W,K)
           const float* __restrict__ bg,       // (3,)
           float*       __restrict__ out,      // (N,H,W,4)
           uint32_t kh0, uint32_t kh1, uint32_t ka0, uint32_t ka1,
           float l0, float l1, float l2, float l3, float l4)
{
    __shared__ float2 zl_s[8 * 256];   // (zinv, logp) per face per thread
    __shared__ float  lut_s[5];

    unsigned tid = threadIdx.x;
    unsigned pix = blockIdx.x * 256u + tid;   // grid is exactly NPIX/256

    if (tid == 0) {
        lut_s[0] = l0; lut_s[1] = l1; lut_s[2] = l2; lut_s[3] = l3; lut_s[4] = l4;
    }
    __syncthreads();

    const float* dp = dists + (size_t)pix * 8;
    const float* zp = zbuf  + (size_t)pix * 8;
    const int*   fp = p2f   + (size_t)pix * 8;

    // ---- phase 1: heaviside via integer threshold; alpha; (zinv,logp) ------
    float alpha = 1.0f;
    float zmax  = -1e30f;
    uint32_t bh = pix * 8u;

#pragma unroll 1
    for (int k = 0; k < 8; ++k) {
        float d = __ldg(dp + k);
        float z = __ldg(zp + k);
        int   f = __ldg(fp + k);
        bool msk = (f >= 0);
        float mask = msk ? 1.0f : 0.0f;
        uint32_t b = bh + (uint32_t)k;
        float x = -d;

        // threshold on m = bits>>9: decision is (m >= m*), |m* - mth| << 64
        float uth = erf_approx(d * 7.0710678f);                 // erf(10d/sqrt2)
        // (uth - LO)*2^22 ; -LO*2^22 = (1-2^-24)*2^22 = 4194303.75 exactly
        int mth = __float2int_rn(__fmaf_rn(uth, 4194304.0f, 4194303.75f));
        int mhi = mth + 64;
        int mlo = mth - 64;

        int cnt = 0;
#pragma unroll
        for (int s = 0; s < 4; ++s) {
            uint32_t bits = tf_xor(kh0, kh1, b + (uint32_t)s * STRIDE_H);
            int m = (int)(bits >> 9);
            if (m >= mhi) {
                cnt++;
            } else if (m > mlo) {   // rare exact fallback (~3e-5 per sample)
                cnt += heaviside_exact(x, (uint32_t)m);
            }
        }

        int idx = msk ? cnt : 0;
        float prob = __fmul_rn((float)cnt * 0.25f, mask);   // exact
        alpha = __fmul_rn(alpha, 1.0f - prob);              // exact product
        float zinvk = __fmul_rn(__fdiv_rn(__fsub_rn(100.0f, z), 99.0f), mask);
        zmax = fmaxf(zmax, zinvk);
        float2 zl; zl.x = zinvk; zl.y = lut_s[idx];
        zl_s[k * 256 + tid] = zl;
    }
    zmax = fmaxf(zmax, 1e-10f);

    // ---- phase 2: random argmax, faces j=0..7, 4 samples, first-max-wins ---
    float b0 = -1e30f, b1 = -1e30f, b2 = -1e30f, b3 = -1e30f;
    int   i0 = 0, i1 = 0, i2 = 0, i3 = 0;
    uint32_t ba = pix * 9u;

#pragma unroll 2
    for (int j = 0; j < 8; ++j) {
        float2 zl = zl_s[j * 256 + tid];
        float zmj = __fadd_rn(zl.y, __fdiv_rn(__fsub_rn(zl.x, zmax), 0.1f));

        uint32_t c = ba + (uint32_t)j;
        float s0 = __fadd_rn(zmj, __fmul_rn(0.1f, m_to_normal(tf_xor(ka0, ka1, c) >> 9)));
        float s1 = __fadd_rn(zmj, __fmul_rn(0.1f, m_to_normal(tf_xor(ka0, ka1, c + STRIDE_A) >> 9)));
        float s2 = __fadd_rn(zmj, __fmul_rn(0.1f, m_to_normal(tf_xor(ka0, ka1, c + 2u * STRIDE_A) >> 9)));
        float s3 = __fadd_rn(zmj, __fmul_rn(0.1f, m_to_normal(tf_xor(ka0, ka1, c + 3u * STRIDE_A) >> 9)));
        if (s0 > b0) { b0 = s0; i0 = j; }
        if (s1 > b1) { b1 = s1; i1 = j; }
        if (s2 > b2) { b2 = s2; i2 = j; }
        if (s3 > b3) { b3 = s3; i3 = j; }
    }
    // Background (j=8): max |0.1*noise| = 0.543 < 0.6; if zm8 can't reach the
    // weakest running best it can never win any sample -> skip (~never taken).
    {
        float zm8 = __fdiv_rn(__fsub_rn(1e-10f, zmax), 0.1f);
        float bmin = fminf(fminf(b0, b1), fminf(b2, b3));
        if (zm8 > bmin - 0.6f) {
            uint32_t c = ba + 8u;
            float s0 = __fadd_rn(zm8, __fmul_rn(0.1f, m_to_normal(tf_xor(ka0, ka1, c) >> 9)));
            float s1 = __fadd_rn(zm8, __fmul_rn(0.1f, m_to_normal(tf_xor(ka0, ka1, c + STRIDE_A) >> 9)));
            float s2 = __fadd_rn(zm8, __fmul_rn(0.1f, m_to_normal(tf_xor(ka0, ka1, c + 2u * STRIDE_A) >> 9)));
            float s3 = __fadd_rn(zm8, __fmul_rn(0.1f, m_to_normal(tf_xor(ka0, ka1, c + 3u * STRIDE_A) >> 9)));
            if (s0 > b0) { i0 = 8; }
            if (s1 > b1) { i1 = 8; }
            if (s2 > b2) { i2 = 8; }
            if (s3 > b3) { i3 = 8; }
        }
    }

    // ---- phase 3: weighted colors (reference summation order k=0..7) ------
    const float* cp = colors + (size_t)pix * 24;
    float r = 0.f, g = 0.f, bl = 0.f;
#pragma unroll 1
    for (int k = 0; k < 8; ++k) {
        int cnt = (i0 == k) + (i1 == k) + (i2 == k) + (i3 == k);
        float wk = __fmul_rn((float)cnt, 0.25f);
        r  = __fadd_rn(r,  __fmul_rn(wk, __ldg(cp + 3 * k + 0)));
        g  = __fadd_rn(g,  __fmul_rn(wk, __ldg(cp + 3 * k + 1)));
        bl = __fadd_rn(bl, __fmul_rn(wk, __ldg(cp + 3 * k + 2)));
    }
    int cntb = (i0 == 8) + (i1 == 8) + (i2 == 8) + (i3 == 8);
    float wb = __fmul_rn((float)cntb, 0.25f);

    float4 o;
    o.x = __fadd_rn(r,  __fmul_rn(wb, bg[0]));
    o.y = __fadd_rn(g,  __fmul_rn(wb, bg[1]));
    o.z = __fadd_rn(bl, __fmul_rn(wb, bg[2]));
    o.w = 1.0f - alpha;
    *(float4*)(out + (size_t)pix * 4) = o;
}

// ---------------------------------------------------------------------------
// Host-side threefry for key derivation (full 2-word output).
// ---------------------------------------------------------------------------
static void threefry_host(uint32_t k0, uint32_t k1, uint32_t x0, uint32_t x1,
                          uint32_t* o0, uint32_t* o1)
{
    uint32_t k2 = k0 ^ k1 ^ 0x1BD11BDAu;
    x0 += k0; x1 += k1;
#define R(r) { x0 += x1; x1 = (x1 << (r)) | (x1 >> (32 - (r))); x1 ^= x0; }
    R(13) R(15) R(26) R(6)
    x0 += k1; x1 += k2 + 1u;
    R(17) R(29) R(16) R(24)
    x0 += k2; x1 += k0 + 2u;
    R(13) R(15) R(26) R(6)
    x0 += k0; x1 += k1 + 3u;
    R(17) R(29) R(16) R(24)
    x0 += k1; x1 += k2 + 4u;
    R(13) R(15) R(26) R(6)
    x0 += k2; x1 += k0 + 5u;
#undef R
    *o0 = x0; *o1 = x1;
}

extern "C" void kernel_launch(void* const* d_in, const int* in_sizes, int n_in,
                              void* d_out, int out_size)
{
    const float* colors = (const float*)d_in[0];
    const float* dists  = (const float*)d_in[1];
    const float* zbuf   = (const float*)d_in[2];
    const int*   p2f    = (const int*)  d_in[3];
    const float* bg     = (const float*)d_in[4];
    float*       out    = (float*)d_out;

    // jax.random.key(1) -> raw key (0, 1); partitionable split.
    uint32_t kh0, kh1, ka0, ka1;
    threefry_host(0u, 1u, 0u, 0u, &kh0, &kh1);   // kh = keys[0]
    threefry_host(0u, 1u, 0u, 1u, &ka0, &ka1);   // ka = keys[1]

    // log(EPS + prob) LUT, prob in {0, 0.25, 0.5, 0.75, 1.0}.
    float l0 = (float)log((double)1e-10f);
    float l1 = (float)log((double)(1e-10f + 0.25f));
    float l2 = (float)log((double)(1e-10f + 0.5f));
    float l3 = (float)log((double)(1e-10f + 0.75f));
    float l4 = (float)log((double)(1e-10f + 1.0f));

    dim3 grid(NPIX / 256);
    rps_kernel<<<grid, 256>>>(colors, dists, zbuf, p2f, bg, out,
                              kh0, kh1, ka0, ka1, l0, l1, l2, l3, l4);
}